// round 10
// baseline (speedup 1.0000x reference)
#include <cuda_runtime.h>
#include <cuda_bf16.h>
#include <math.h>

// Problem constants
#define BB 8
#define NX 1024
#define NY 1024
#define C1 1024
#define C2 1024
#define HH 16
#define DD 32
#define HD (HH*DD)          // 512
#define WW 4
#define MROWS (BB*NX)       // 8192
#define EPS 1e-5f

// ---------------- scratch (one big __device__ array, no allocations) -------
#define OFF_XN  0
#define OFF_YN  (OFF_XN + 8388608)
#define OFF_Q   (OFF_YN + 8388608)
#define OFF_K   (OFF_Q  + 4194304)
#define OFF_V   (OFF_K  + 4194304)
#define OFF_O   (OFF_V  + 4194304)
#define OFF_H0  (OFF_O  + 4194304)
#define OFF_H1  (OFF_H0 + 8388608)
#define SCRATCH_FLOATS (OFF_H1 + 33554432)

__device__ float g_scratch[SCRATCH_FLOATS];

// ---------------- layernorm ------------------------------------------------
__device__ __forceinline__ float block_reduce_sum(float v, float* red) {
    #pragma unroll
    for (int o = 16; o > 0; o >>= 1) v += __shfl_xor_sync(0xffffffffu, v, o);
    int lane = threadIdx.x & 31, w = threadIdx.x >> 5;
    if (lane == 0) red[w] = v;
    __syncthreads();
    if (w == 0) {
        v = red[lane & 7];
        #pragma unroll
        for (int o = 4; o > 0; o >>= 1) v += __shfl_xor_sync(0xffffffffu, v, o);
        if (lane == 0) red[0] = v;
    }
    __syncthreads();
    float r = red[0];
    __syncthreads();
    return r;
}

// per-row LN body (C = 1024, 256 threads, 4 elems/thread)
__device__ __forceinline__ void ln_row(const float* __restrict__ xr,
                                       float* __restrict__ outr,
                                       const float* __restrict__ g,
                                       const float* __restrict__ be,
                                       float* red) {
    const int tid = threadIdx.x;
    float4 v = *(const float4*)(xr + tid * 4);
    float s = v.x + v.y + v.z + v.w;
    float total = block_reduce_sum(s, red);
    float mu = total * (1.0f / (float)C1);
    float dx = v.x - mu, dy = v.y - mu, dz = v.z - mu, dw = v.w - mu;
    float ss = dx*dx + dy*dy + dz*dz + dw*dw;
    float tot2 = block_reduce_sum(ss, red);
    float rstd = rsqrtf(tot2 * (1.0f / (float)C1) + EPS);
    float4 gg = *(const float4*)(g + tid * 4);
    float4 bb = *(const float4*)(be + tid * 4);
    float4 o;
    o.x = dx * rstd * gg.x + bb.x;
    o.y = dy * rstd * gg.y + bb.y;
    o.z = dz * rstd * gg.z + bb.z;
    o.w = dw * rstd * gg.w + bb.w;
    *(float4*)(outr + tid * 4) = o;
}

__global__ __launch_bounds__(256) void ln_kernel(const float* __restrict__ x,
                                                 float* __restrict__ out,
                                                 const float* __restrict__ g,
                                                 const float* __restrict__ be) {
    __shared__ float red[8];
    const int row = blockIdx.x;
    ln_row(x + (size_t)row * C1, out + (size_t)row * C1, g, be, red);
}

// merged LN for both inputs: rows [0,MROWS) = x -> xn, [MROWS,2*MROWS) = y -> yn
__global__ __launch_bounds__(256) void ln2_kernel(const float* __restrict__ x,
                                                  float* __restrict__ xn,
                                                  const float* __restrict__ g1,
                                                  const float* __restrict__ be1,
                                                  const float* __restrict__ y,
                                                  float* __restrict__ yn,
                                                  const float* __restrict__ g2,
                                                  const float* __restrict__ be2) {
    __shared__ float red[8];
    const int row = blockIdx.x;
    if (row < MROWS) {
        ln_row(x + (size_t)row * C1, xn + (size_t)row * C1, g1, be1, red);
    } else {
        const int r2 = row - MROWS;
        ln_row(y + (size_t)r2 * C2, yn + (size_t)r2 * C2, g2, be2, red);
    }
}

// ---------------- generic SGEMM: A[M,K] x B[K,N] row-major -----------------
// 128x128 tile, K-step 16, 256 threads, 8x8 microtile. K is compile-time.
// Double-buffered smem, mainloop explicitly unrolled by 2 so both buffers are
// compile-time constants (immediate-offset LDS). Running global pointers
// (strength-reduced). As rows padded to 132 floats so each k-row base is
// 16B-aligned -> fragment loads are LDS.128.
// WSRC 0: B is a plain row-major [K,N] matrix.
// WSRC 1: B is a packed per-head weight [H, K, 32]; logical column n maps to
//         B[n>>5][k][n&31] (4-wide groups stay within one head: aligned f4).
// MODE 0: C = acc / 1: +bias+res / 2: gelu(acc+bias)
template<int MODE, int WSRC, int K>
__device__ __forceinline__ void sgemm_body(
    const float* __restrict__ A, const float* __restrict__ B,
    float* __restrict__ C, int N,
    const float* __restrict__ bias, const float* __restrict__ res,
    float (*As)[16][132], float (*Bs)[16][128]) {
    constexpr int NK = K >> 4;
    static_assert((NK & 1) == 0, "NK must be even");
    const int tid = threadIdx.x;
    const int tx = tid & 15, ty = tid >> 4;
    const int bx = blockIdx.x, by = blockIdx.y;
    float acc[8][8];
    #pragma unroll
    for (int i = 0; i < 8; i++)
        #pragma unroll
        for (int j = 0; j < 8; j++) acc[i][j] = 0.0f;

    const int arow = tid >> 2;             // 0..63
    const int acol = (tid & 3) << 2;       // 0,4,8,12
    const int brow = tid >> 5;             // 0..7
    const int bcol = (tid & 31) << 2;      // 0..124

    // running global pointers (strength-reduced; advance per K-tile)
    const float* aP0 = A + (size_t)(by * 128 + arow) * K + acol;
    const float* aP1 = aP0 + (size_t)64 * K;
    const int nn = bx * 128 + bcol;
    const float* bP0;
    const float* bP1;
    long bAdv;
    if (WSRC == 0) {
        bP0 = B + (size_t)brow * N + nn;
        bP1 = bP0 + (size_t)8 * N;
        bAdv = (long)16 * N;
    } else {
        bP0 = B + ((size_t)(nn >> 5) * K + brow) * 32 + (nn & 31);
        bP1 = bP0 + 8 * 32;
        bAdv = 16 * 32;
    }

    float4 pa[2], pb[2];
    auto prefetch = [&]() {
        pa[0] = *(const float4*)aP0;
        pa[1] = *(const float4*)aP1;
        pb[0] = *(const float4*)bP0;
        pb[1] = *(const float4*)bP1;
        aP0 += 16; aP1 += 16;
        bP0 += bAdv; bP1 += bAdv;
    };
    #define STORE_TILE(BUF)                                                   \
        {                                                                     \
            As[BUF][acol + 0][arow]      = pa[0].x;                           \
            As[BUF][acol + 1][arow]      = pa[0].y;                           \
            As[BUF][acol + 2][arow]      = pa[0].z;                           \
            As[BUF][acol + 3][arow]      = pa[0].w;                           \
            As[BUF][acol + 0][arow + 64] = pa[1].x;                           \
            As[BUF][acol + 1][arow + 64] = pa[1].y;                           \
            As[BUF][acol + 2][arow + 64] = pa[1].z;                           \
            As[BUF][acol + 3][arow + 64] = pa[1].w;                           \
            *(float4*)&Bs[BUF][brow][bcol]     = pb[0];                       \
            *(float4*)&Bs[BUF][brow + 8][bcol] = pb[1];                       \
        }
    #define COMPUTE_TILE(BUF)                                                 \
        _Pragma("unroll")                                                     \
        for (int kk = 0; kk < 16; kk++) {                                     \
            float af[8], bf[8];                                               \
            ((float4*)af)[0] = *(const float4*)&As[BUF][kk][ty * 8];          \
            ((float4*)af)[1] = *(const float4*)&As[BUF][kk][ty * 8 + 4];      \
            ((float4*)bf)[0] = *(const float4*)&Bs[BUF][kk][tx * 8];          \
            ((float4*)bf)[1] = *(const float4*)&Bs[BUF][kk][tx * 8 + 4];      \
            _Pragma("unroll")                                                 \
            for (int i = 0; i < 8; i++)                                       \
                _Pragma("unroll")                                             \
                for (int j = 0; j < 8; j++)                                   \
                    acc[i][j] = fmaf(af[i], bf[j], acc[i][j]);                \
        }

    prefetch();          // tile 0
    STORE_TILE(0);
    __syncthreads();

    for (int t = 0; t < NK; t += 2) {
        // even tile in buffer 0; odd tile (t+1 < NK always, NK even) into 1
        prefetch();      // tile t+1
        COMPUTE_TILE(0);
        STORE_TILE(1);
        __syncthreads();
        if (t + 2 < NK) {
            prefetch();  // tile t+2
            COMPUTE_TILE(1);
            STORE_TILE(0);
            __syncthreads();
        } else {
            COMPUTE_TILE(1);
        }
    }
    #undef STORE_TILE
    #undef COMPUTE_TILE

    // vectorized epilogue: two float4 stores per row
    const int col0 = bx * 128 + tx * 8;
    float4 bias4a, bias4b;
    if (MODE == 1 || MODE == 2) {
        bias4a = *(const float4*)(bias + col0);
        bias4b = *(const float4*)(bias + col0 + 4);
    }
    #pragma unroll
    for (int i = 0; i < 8; i++) {
        int row = by * 128 + ty * 8 + i;
        float v[8];
        #pragma unroll
        for (int j = 0; j < 8; j++) v[j] = acc[i][j];
        if (MODE == 1) {
            float4 r4a = *(const float4*)(res + (size_t)row * N + col0);
            float4 r4b = *(const float4*)(res + (size_t)row * N + col0 + 4);
            v[0] += bias4a.x + r4a.x; v[1] += bias4a.y + r4a.y;
            v[2] += bias4a.z + r4a.z; v[3] += bias4a.w + r4a.w;
            v[4] += bias4b.x + r4b.x; v[5] += bias4b.y + r4b.y;
            v[6] += bias4b.z + r4b.z; v[7] += bias4b.w + r4b.w;
        }
        if (MODE == 2) {
            v[0] += bias4a.x; v[1] += bias4a.y; v[2] += bias4a.z; v[3] += bias4a.w;
            v[4] += bias4b.x; v[5] += bias4b.y; v[6] += bias4b.z; v[7] += bias4b.w;
            #pragma unroll
            for (int j = 0; j < 8; j++)
                v[j] = 0.5f * v[j] * (1.0f + erff(v[j] * 0.70710678118654752f));
        }
        *(float4*)(C + (size_t)row * N + col0)     = make_float4(v[0], v[1], v[2], v[3]);
        *(float4*)(C + (size_t)row * N + col0 + 4) = make_float4(v[4], v[5], v[6], v[7]);
    }
}

template<int MODE, int WSRC, int K>
__global__ __launch_bounds__(256, 2) void sgemm_kernel(
    const float* __restrict__ A, const float* __restrict__ B,
    float* __restrict__ C, int N,
    const float* __restrict__ bias, const float* __restrict__ res) {
    __shared__ float As[2][16][132];
    __shared__ float Bs[2][16][128];
    sgemm_body<MODE, WSRC, K>(A, B, C, N, bias, res, As, Bs);
}

// fused QKV: one launch, z selects {xn*Wq->q, yn*Wk->k, yn*Wv->v}.
// K/V CTAs co-resident -> concurrent L2 reuse of yn.
__global__ __launch_bounds__(256, 2) void qkv_kernel(
    const float* __restrict__ xn, const float* __restrict__ yn,
    const float* __restrict__ Wq, const float* __restrict__ Wk,
    const float* __restrict__ Wv,
    float* __restrict__ q, float* __restrict__ k, float* __restrict__ v) {
    __shared__ float As[2][16][132];
    __shared__ float Bs[2][16][128];
    const int z = blockIdx.z;
    const float* A = (z == 0) ? xn : yn;
    const float* B = (z == 0) ? Wq : (z == 1) ? Wk : Wv;
    float* C = (z == 0) ? q : (z == 1) ? k : v;
    sgemm_body<0, 1, C1>(A, B, C, HD, nullptr, nullptr, As, Bs);
}

// ---------------- flash attention ------------------------------------------
// Q,K,V layout: [B, N, H*D] row-major (head columns h*32..h*32+31).
// grid (NX/128, H, B), 256 threads. Key tiles of 128. Scores s[8][8] stay in
// registers; online softmax is done with half-warp shfl_xor reductions (row
// ty*8+i is partitioned across the 16 tx lanes of one half-warp), so the only
// smem traffic for P is a single vectorized store feeding P@V. m/l state is
// register-replicated across the 16 lanes. 3 barriers per key tile.
// vS stride 34 (even) so paired float2 loads are 8B-aligned; S/qT/kT stride
// 132 so row bases are 16B-aligned for LDS.128 fragment loads.
#define ATTN_SMEM ((2*32*132 + 128*34 + 128*132) * 4)

__global__ __launch_bounds__(256) void attn_kernel(const float* __restrict__ Q,
                                                   const float* __restrict__ K,
                                                   const float* __restrict__ V,
                                                   float* __restrict__ O) {
    extern __shared__ float sm[];
    float* qT = sm;                   // [32][132]
    float* kT = qT + 32 * 132;        // [32][132]
    float* vS = kT + 32 * 132;        // [128][34]
    float* S  = vS + 128 * 34;        // [128][132]  (holds P = exp(s - m))

    const int tid = threadIdx.x;
    const int tx = tid & 15, ty = tid >> 4;
    const int b = blockIdx.z, h = blockIdx.y, qt = blockIdx.x;
    const float* qb = Q + ((size_t)(b * NX) + qt * 128) * HD + h * DD;
    const float* kb = K + ((size_t)(b * NY)) * HD + h * DD;
    const float* vb = V + ((size_t)(b * NY)) * HD + h * DD;
    const float scale = 0.17677669529663687f;   // 1/sqrt(32)

    {
        int d4 = (tid & 7) * 4, n0 = tid >> 3;
        #pragma unroll
        for (int rep = 0; rep < 4; rep++) {
            int n = n0 + rep * 32;
            float4 v = *(const float4*)(qb + (size_t)n * HD + d4);
            qT[(d4 + 0) * 132 + n] = v.x * scale;
            qT[(d4 + 1) * 132 + n] = v.y * scale;
            qT[(d4 + 2) * 132 + n] = v.z * scale;
            qT[(d4 + 3) * 132 + n] = v.w * scale;
        }
    }
    float m_i[8], l_i[8];
    float oacc[8][2];
    #pragma unroll
    for (int i = 0; i < 8; i++) {
        m_i[i] = -3.0e38f;
        l_i[i] = 0.0f;
        oacc[i][0] = 0.0f;
        oacc[i][1] = 0.0f;
    }

    for (int t = 0; t < 8; t++) {
        __syncthreads();   // previous P@V done: safe to overwrite kT/vS/S
        {
            int d4 = (tid & 7) * 4, n0 = tid >> 3;
            #pragma unroll
            for (int rep = 0; rep < 4; rep++) {
                int n = n0 + rep * 32;
                float4 kv = *(const float4*)(kb + (size_t)(t * 128 + n) * HD + d4);
                kT[(d4 + 0) * 132 + n] = kv.x;
                kT[(d4 + 1) * 132 + n] = kv.y;
                kT[(d4 + 2) * 132 + n] = kv.z;
                kT[(d4 + 3) * 132 + n] = kv.w;
                float4 vv = *(const float4*)(vb + (size_t)(t * 128 + n) * HD + d4);
                vS[n * 34 + d4 + 0] = vv.x;
                vS[n * 34 + d4 + 1] = vv.y;
                vS[n * 34 + d4 + 2] = vv.z;
                vS[n * 34 + d4 + 3] = vv.w;
            }
        }
        __syncthreads();
        // s = q k^T  (8x8 microtile per thread, vectorized fragment loads)
        float s[8][8];
        #pragma unroll
        for (int i = 0; i < 8; i++)
            #pragma unroll
            for (int j = 0; j < 8; j++) s[i][j] = 0.0f;
        #pragma unroll 8
        for (int kk = 0; kk < 32; kk++) {
            float af[8], bf[8];
            ((float4*)af)[0] = *(const float4*)&qT[kk * 132 + ty * 8];
            ((float4*)af)[1] = *(const float4*)&qT[kk * 132 + ty * 8 + 4];
            ((float4*)bf)[0] = *(const float4*)&kT[kk * 132 + tx * 8];
            ((float4*)bf)[1] = *(const float4*)&kT[kk * 132 + tx * 8 + 4];
            #pragma unroll
            for (int i = 0; i < 8; i++)
                #pragma unroll
                for (int j = 0; j < 8; j++)
                    s[i][j] = fmaf(af[i], bf[j], s[i][j]);
        }
        // in-register online softmax: row ty*8+i spans the 16 tx lanes of a
        // half-warp; shfl_xor strides 1,2,4,8 reduce across the row
        #pragma unroll
        for (int i = 0; i < 8; i++) {
            float mx = s[i][0];
            #pragma unroll
            for (int j = 1; j < 8; j++) mx = fmaxf(mx, s[i][j]);
            #pragma unroll
            for (int o = 1; o < 16; o <<= 1)
                mx = fmaxf(mx, __shfl_xor_sync(0xffffffffu, mx, o));
            float newm = fmaxf(m_i[i], mx);
            float alpha = __expf(m_i[i] - newm);
            float l = 0.0f;
            #pragma unroll
            for (int j = 0; j < 8; j++) {
                float p = __expf(s[i][j] - newm);
                s[i][j] = p;
                l += p;
            }
            #pragma unroll
            for (int o = 1; o < 16; o <<= 1)
                l += __shfl_xor_sync(0xffffffffu, l, o);
            l_i[i] = l_i[i] * alpha + l;
            m_i[i] = newm;
            oacc[i][0] *= alpha;
            oacc[i][1] *= alpha;
        }
        // store P (already exponentiated) for the P@V pass
        #pragma unroll
        for (int i = 0; i < 8; i++) {
            *(float4*)&S[(ty * 8 + i) * 132 + tx * 8]     = make_float4(s[i][0], s[i][1], s[i][2], s[i][3]);
            *(float4*)&S[(ty * 8 + i) * 132 + tx * 8 + 4] = make_float4(s[i][4], s[i][5], s[i][6], s[i][7]);
        }
        __syncthreads();
        // O += P @ V, j in chunks of 4: S rows via LDS.128, V pairs via LDS.64
        #pragma unroll 4
        for (int j4 = 0; j4 < 32; j4++) {
            float2 vv[4];
            #pragma unroll
            for (int jj = 0; jj < 4; jj++)
                vv[jj] = *(const float2*)&vS[(j4 * 4 + jj) * 34 + tx * 2];
            #pragma unroll
            for (int i = 0; i < 8; i++) {
                float4 p4 = *(const float4*)&S[(ty * 8 + i) * 132 + j4 * 4];
                oacc[i][0] = fmaf(p4.x, vv[0].x, oacc[i][0]);
                oacc[i][1] = fmaf(p4.x, vv[0].y, oacc[i][1]);
                oacc[i][0] = fmaf(p4.y, vv[1].x, oacc[i][0]);
                oacc[i][1] = fmaf(p4.y, vv[1].y, oacc[i][1]);
                oacc[i][0] = fmaf(p4.z, vv[2].x, oacc[i][0]);
                oacc[i][1] = fmaf(p4.z, vv[2].y, oacc[i][1]);
                oacc[i][0] = fmaf(p4.w, vv[3].x, oacc[i][0]);
                oacc[i][1] = fmaf(p4.w, vv[3].y, oacc[i][1]);
            }
        }
    }
    float* ob = O + ((size_t)(b * NX) + qt * 128) * HD + h * DD;
    #pragma unroll
    for (int i = 0; i < 8; i++) {
        int r = ty * 8 + i;
        float inv = 1.0f / l_i[i];
        ob[(size_t)r * HD + tx * 2]     = oacc[i][0] * inv;
        ob[(size_t)r * HD + tx * 2 + 1] = oacc[i][1] * inv;
    }
}

// ---------------- launch ----------------------------------------------------
extern "C" void kernel_launch(void* const* d_in, const int* in_sizes, int n_in,
                              void* d_out, int out_size) {
    const float* x   = (const float*)d_in[0];
    const float* y   = (const float*)d_in[1];
    const float* Wq  = (const float*)d_in[2];
    const float* Wk  = (const float*)d_in[3];
    const float* Wv  = (const float*)d_in[4];
    const float* W1  = (const float*)d_in[5];
    const float* b1  = (const float*)d_in[6];
    const float* g1  = (const float*)d_in[7];
    const float* be1 = (const float*)d_in[8];
    const float* g2  = (const float*)d_in[9];
    const float* be2 = (const float*)d_in[10];
    const float* g3  = (const float*)d_in[11];
    const float* be3 = (const float*)d_in[12];
    const float* W2  = (const float*)d_in[13];
    const float* b2  = (const float*)d_in[14];
    const float* W3  = (const float*)d_in[15];
    const float* b3  = (const float*)d_in[16];
    float* out = (float*)d_out;

    float* base = nullptr;
    cudaGetSymbolAddress((void**)&base, g_scratch);
    float* xn = base + OFF_XN;
    float* yn = base + OFF_YN;
    float* q  = base + OFF_Q;
    float* k  = base + OFF_K;
    float* v  = base + OFF_V;
    float* o  = base + OFF_O;
    float* h0 = base + OFF_H0;
    float* h1 = base + OFF_H1;

    cudaFuncSetAttribute(attn_kernel, cudaFuncAttributeMaxDynamicSharedMemorySize, ATTN_SMEM);

    // 1. LayerNorms of both inputs (single launch)
    ln2_kernel<<<2 * MROWS, 256>>>(x, xn, g1, be1, y, yn, g2, be2);

    // 2. QKV projections (single launch, z-dispatch; packed [H,C,32] weights)
    qkv_kernel<<<dim3(HD / 128, MROWS / 128, 3), 256>>>(xn, yn, Wq, Wk, Wv, q, k, v);

    // 3. Attention
    attn_kernel<<<dim3(NX / 128, HH, BB), 256, ATTN_SMEM>>>(q, k, v, o);

    // 4. out0 = xn + o @ W1 + b1   (stored in d_out)
    sgemm_kernel<1, 0, HD><<<dim3(C1 / 128, MROWS / 128), 256>>>(o, W1, out, C1, b1, xn);

    // 5. h0 = LN(out0)
    ln_kernel<<<MROWS, 256>>>(out, h0, g3, be3);

    // 6. h1 = gelu(h0 @ W2 + b2)
    sgemm_kernel<2, 0, C1><<<dim3((WW * C1) / 128, MROWS / 128), 256>>>(h0, W2, h1, WW * C1, b2, nullptr);

    // 7. out = out0 + h1 @ W3 + b3
    sgemm_kernel<1, 0, WW * C1><<<dim3(C1 / 128, MROWS / 128), 256>>>(h1, W3, out, C1, b3, out);
}

// round 15
// speedup vs baseline: 1.1675x; 1.1675x over previous
#include <cuda_runtime.h>
#include <cuda_bf16.h>
#include <math.h>

// Problem constants
#define BB 8
#define NX 1024
#define NY 1024
#define C1 1024
#define C2 1024
#define HH 16
#define DD 32
#define HD (HH*DD)          // 512
#define WW 4
#define MROWS (BB*NX)       // 8192
#define EPS 1e-5f

// ---------------- scratch (one big __device__ array, no allocations) -------
#define OFF_XN  0
#define OFF_YN  (OFF_XN + 8388608)
#define OFF_Q   (OFF_YN + 8388608)
#define OFF_K   (OFF_Q  + 4194304)
#define OFF_V   (OFF_K  + 4194304)
#define OFF_O   (OFF_V  + 4194304)
#define OFF_H0  (OFF_O  + 4194304)
#define OFF_H1  (OFF_H0 + 8388608)
#define SCRATCH_FLOATS (OFF_H1 + 33554432)

__device__ float g_scratch[SCRATCH_FLOATS];

// ---------------- layernorm ------------------------------------------------
__device__ __forceinline__ float block_reduce_sum(float v, float* red) {
    #pragma unroll
    for (int o = 16; o > 0; o >>= 1) v += __shfl_xor_sync(0xffffffffu, v, o);
    int lane = threadIdx.x & 31, w = threadIdx.x >> 5;
    if (lane == 0) red[w] = v;
    __syncthreads();
    if (w == 0) {
        v = red[lane & 7];
        #pragma unroll
        for (int o = 4; o > 0; o >>= 1) v += __shfl_xor_sync(0xffffffffu, v, o);
        if (lane == 0) red[0] = v;
    }
    __syncthreads();
    float r = red[0];
    __syncthreads();
    return r;
}

// per-row LN body (C = 1024, 256 threads, 4 elems/thread)
__device__ __forceinline__ void ln_row(const float* __restrict__ xr,
                                       float* __restrict__ outr,
                                       const float* __restrict__ g,
                                       const float* __restrict__ be,
                                       float* red) {
    const int tid = threadIdx.x;
    float4 v = *(const float4*)(xr + tid * 4);
    float s = v.x + v.y + v.z + v.w;
    float total = block_reduce_sum(s, red);
    float mu = total * (1.0f / (float)C1);
    float dx = v.x - mu, dy = v.y - mu, dz = v.z - mu, dw = v.w - mu;
    float ss = dx*dx + dy*dy + dz*dz + dw*dw;
    float tot2 = block_reduce_sum(ss, red);
    float rstd = rsqrtf(tot2 * (1.0f / (float)C1) + EPS);
    float4 gg = *(const float4*)(g + tid * 4);
    float4 bb = *(const float4*)(be + tid * 4);
    float4 o;
    o.x = dx * rstd * gg.x + bb.x;
    o.y = dy * rstd * gg.y + bb.y;
    o.z = dz * rstd * gg.z + bb.z;
    o.w = dw * rstd * gg.w + bb.w;
    *(float4*)(outr + tid * 4) = o;
}

__global__ __launch_bounds__(256) void ln_kernel(const float* __restrict__ x,
                                                 float* __restrict__ out,
                                                 const float* __restrict__ g,
                                                 const float* __restrict__ be) {
    __shared__ float red[8];
    const int row = blockIdx.x;
    ln_row(x + (size_t)row * C1, out + (size_t)row * C1, g, be, red);
}

// merged LN for both inputs: rows [0,MROWS) = x -> xn, [MROWS,2*MROWS) = y -> yn
__global__ __launch_bounds__(256) void ln2_kernel(const float* __restrict__ x,
                                                  float* __restrict__ xn,
                                                  const float* __restrict__ g1,
                                                  const float* __restrict__ be1,
                                                  const float* __restrict__ y,
                                                  float* __restrict__ yn,
                                                  const float* __restrict__ g2,
                                                  const float* __restrict__ be2) {
    __shared__ float red[8];
    const int row = blockIdx.x;
    if (row < MROWS) {
        ln_row(x + (size_t)row * C1, xn + (size_t)row * C1, g1, be1, red);
    } else {
        const int r2 = row - MROWS;
        ln_row(y + (size_t)r2 * C2, yn + (size_t)r2 * C2, g2, be2, red);
    }
}

// ---------------- tf32 helpers ---------------------------------------------
__device__ __forceinline__ void tf32split(float x, unsigned& hi, unsigned& lo) {
    unsigned h;
    asm("cvt.rna.tf32.f32 %0, %1;" : "=r"(h) : "f"(x));
    float r = x - __uint_as_float(h);
    unsigned l;
    asm("cvt.rna.tf32.f32 %0, %1;" : "=r"(l) : "f"(r));
    hi = h; lo = l;
}

__device__ __forceinline__ void mma_tf32(float* d, const unsigned* a,
                                         const unsigned* b) {
    asm volatile(
        "mma.sync.aligned.m16n8k8.row.col.f32.tf32.tf32.f32 "
        "{%0,%1,%2,%3}, {%4,%5,%6,%7}, {%8,%9}, {%0,%1,%2,%3};"
        : "+f"(d[0]), "+f"(d[1]), "+f"(d[2]), "+f"(d[3])
        : "r"(a[0]), "r"(a[1]), "r"(a[2]), "r"(a[3]), "r"(b[0]), "r"(b[1]));
}

// ---------------- tensor-core SGEMM: A[M,K] x B[K,N] -----------------------
// 128x128 CTA tile, K-step 16, 256 threads (8 warps in a 4(M) x 2(N) grid,
// each warp owns 32x64). mma.sync m16n8k8 tf32 with 3xTF32 split
// (Ah*Bh + Ah*Bl + Al*Bh) for ~fp32 accuracy. Double-buffered smem, unroll-2
// mainloop (compile-time buffer indices).
// A tile row-major [128][20]: fragment load addr 20*grp+tig covers all 32
// banks (conflict-free). B tile [16][136]: 136 mod 32 = 8 so fragment load
// addr 8*tig+grp covers all 32 banks (conflict-free). K compile-time, NK even.
// B splits for all 8 nt sub-tiles are hoisted ahead of the mma chain so the
// HMMA stream stays dense and the B-fragment LDS batch issues early.
// WSRC 0: B is a plain row-major [K,N] matrix.
// WSRC 1: B is a packed per-head weight [H, K, 32]; column n -> B[n>>5][k][n&31].
// MODE 0: C = acc / 1: +bias+res / 2: gelu(acc+bias)
template<int MODE, int WSRC, int K>
__device__ __forceinline__ void sgemm_body(
    const float* __restrict__ A, const float* __restrict__ B,
    float* __restrict__ C, int N,
    const float* __restrict__ bias, const float* __restrict__ res,
    float (*As)[128][20], float (*Bs)[16][136]) {
    constexpr int NK = K >> 4;
    static_assert((NK & 1) == 0, "NK must be even");
    const int tid = threadIdx.x;
    const int bx = blockIdx.x, by = blockIdx.y;
    const int lane = tid & 31;
    const int grp = lane >> 2;          // 0..7
    const int tig = lane & 3;           // 0..3
    const int w = tid >> 5;             // 0..7
    const int wm = (w & 3) * 32;        // warp M offset
    const int wn = (w >> 2) * 64;       // warp N offset

    float acc[2][8][4];
    #pragma unroll
    for (int mt = 0; mt < 2; mt++)
        #pragma unroll
        for (int nt = 0; nt < 8; nt++)
            #pragma unroll
            for (int e = 0; e < 4; e++) acc[mt][nt][e] = 0.0f;

    // loaders: A row-major, 128 rows x 16 cols per tile
    const int arow = tid >> 1;            // 0..127
    const int acg  = (tid & 1) * 8;       // 0 or 8
    const int brow = tid >> 5;            // 0..7
    const int bcol = (tid & 31) << 2;     // 0..124

    const float* aP = A + (size_t)(by * 128 + arow) * K + acg;
    const int nn = bx * 128 + bcol;
    const float* bP0;
    const float* bP1;
    long bAdv;
    if (WSRC == 0) {
        bP0 = B + (size_t)brow * N + nn;
        bP1 = bP0 + (size_t)8 * N;
        bAdv = (long)16 * N;
    } else {
        bP0 = B + ((size_t)(nn >> 5) * K + brow) * 32 + (nn & 31);
        bP1 = bP0 + 8 * 32;
        bAdv = 16 * 32;
    }

    float4 pa[2], pb[2];
    auto prefetch = [&]() {
        pa[0] = *(const float4*)aP;
        pa[1] = *(const float4*)(aP + 4);
        pb[0] = *(const float4*)bP0;
        pb[1] = *(const float4*)bP1;
        aP += 16;
        bP0 += bAdv; bP1 += bAdv;
    };
    #define STORE_TILE(BUF)                                                   \
        {                                                                     \
            *(float4*)&As[BUF][arow][acg]     = pa[0];                        \
            *(float4*)&As[BUF][arow][acg + 4] = pa[1];                        \
            *(float4*)&Bs[BUF][brow][bcol]     = pb[0];                       \
            *(float4*)&Bs[BUF][brow + 8][bcol] = pb[1];                       \
        }
    #define COMPUTE_TILE(BUF)                                                 \
        _Pragma("unroll")                                                     \
        for (int ks = 0; ks < 2; ks++) {                                      \
            unsigned ah[2][4], al[2][4];                                      \
            _Pragma("unroll")                                                 \
            for (int mt = 0; mt < 2; mt++) {                                  \
                float a0 = As[BUF][wm + mt * 16 + grp][ks * 8 + tig];         \
                float a1 = As[BUF][wm + mt * 16 + grp + 8][ks * 8 + tig];     \
                float a2 = As[BUF][wm + mt * 16 + grp][ks * 8 + tig + 4];     \
                float a3 = As[BUF][wm + mt * 16 + grp + 8][ks * 8 + tig + 4]; \
                tf32split(a0, ah[mt][0], al[mt][0]);                          \
                tf32split(a1, ah[mt][1], al[mt][1]);                          \
                tf32split(a2, ah[mt][2], al[mt][2]);                          \
                tf32split(a3, ah[mt][3], al[mt][3]);                          \
            }                                                                 \
            unsigned bh[8][2], bl[8][2];                                      \
            _Pragma("unroll")                                                 \
            for (int nt = 0; nt < 8; nt++) {                                  \
                float b0 = Bs[BUF][ks * 8 + tig][wn + nt * 8 + grp];          \
                float b1 = Bs[BUF][ks * 8 + tig + 4][wn + nt * 8 + grp];      \
                tf32split(b0, bh[nt][0], bl[nt][0]);                          \
                tf32split(b1, bh[nt][1], bl[nt][1]);                          \
            }                                                                 \
            _Pragma("unroll")                                                 \
            for (int nt = 0; nt < 8; nt++) {                                  \
                _Pragma("unroll")                                             \
                for (int mt = 0; mt < 2; mt++) {                              \
                    mma_tf32(acc[mt][nt], ah[mt], bh[nt]);                    \
                    mma_tf32(acc[mt][nt], ah[mt], bl[nt]);                    \
                    mma_tf32(acc[mt][nt], al[mt], bh[nt]);                    \
                }                                                             \
            }                                                                 \
        }

    prefetch();          // tile 0
    STORE_TILE(0);
    __syncthreads();

    for (int t = 0; t < NK; t += 2) {
        prefetch();      // tile t+1
        COMPUTE_TILE(0);
        STORE_TILE(1);
        __syncthreads();
        if (t + 2 < NK) {
            prefetch();  // tile t+2
            COMPUTE_TILE(1);
            STORE_TILE(0);
            __syncthreads();
        } else {
            COMPUTE_TILE(1);
        }
    }
    #undef STORE_TILE
    #undef COMPUTE_TILE

    // epilogue: fragment layout c0,c1 = row grp cols 2*tig,2*tig+1;
    // c2,c3 = row grp+8 -> float2 stores
    #pragma unroll
    for (int mt = 0; mt < 2; mt++) {
        #pragma unroll
        for (int nt = 0; nt < 8; nt++) {
            int r0 = by * 128 + wm + mt * 16 + grp;
            int r1 = r0 + 8;
            int c  = bx * 128 + wn + nt * 8 + tig * 2;
            float v0 = acc[mt][nt][0], v1 = acc[mt][nt][1];
            float v2 = acc[mt][nt][2], v3 = acc[mt][nt][3];
            if (MODE == 1 || MODE == 2) {
                float2 b2 = *(const float2*)(bias + c);
                v0 += b2.x; v1 += b2.y; v2 += b2.x; v3 += b2.y;
            }
            if (MODE == 1) {
                float2 ra = *(const float2*)(res + (size_t)r0 * N + c);
                float2 rb = *(const float2*)(res + (size_t)r1 * N + c);
                v0 += ra.x; v1 += ra.y; v2 += rb.x; v3 += rb.y;
            }
            if (MODE == 2) {
                v0 = 0.5f * v0 * (1.0f + erff(v0 * 0.70710678118654752f));
                v1 = 0.5f * v1 * (1.0f + erff(v1 * 0.70710678118654752f));
                v2 = 0.5f * v2 * (1.0f + erff(v2 * 0.70710678118654752f));
                v3 = 0.5f * v3 * (1.0f + erff(v3 * 0.70710678118654752f));
            }
            *(float2*)(C + (size_t)r0 * N + c) = make_float2(v0, v1);
            *(float2*)(C + (size_t)r1 * N + c) = make_float2(v2, v3);
        }
    }
}

template<int MODE, int WSRC, int K>
__global__ __launch_bounds__(256, 2) void sgemm_kernel(
    const float* __restrict__ A, const float* __restrict__ B,
    float* __restrict__ C, int N,
    const float* __restrict__ bias, const float* __restrict__ res) {
    __shared__ float As[2][128][20];
    __shared__ float Bs[2][16][136];
    sgemm_body<MODE, WSRC, K>(A, B, C, N, bias, res, As, Bs);
}

// fused QKV: one launch, z selects {xn*Wq->q, yn*Wk->k, yn*Wv->v}.
__global__ __launch_bounds__(256, 2) void qkv_kernel(
    const float* __restrict__ xn, const float* __restrict__ yn,
    const float* __restrict__ Wq, const float* __restrict__ Wk,
    const float* __restrict__ Wv,
    float* __restrict__ q, float* __restrict__ k, float* __restrict__ v) {
    __shared__ float As[2][128][20];
    __shared__ float Bs[2][16][136];
    const int z = blockIdx.z;
    const float* A = (z == 0) ? xn : yn;
    const float* B = (z == 0) ? Wq : (z == 1) ? Wk : Wv;
    float* C = (z == 0) ? q : (z == 1) ? k : v;
    sgemm_body<0, 1, C1>(A, B, C, HD, nullptr, nullptr, As, Bs);
}

// ---------------- flash attention (unchanged from passing R10) -------------
#define ATTN_SMEM ((2*32*132 + 128*34 + 128*132) * 4)

__global__ __launch_bounds__(256) void attn_kernel(const float* __restrict__ Q,
                                                   const float* __restrict__ K,
                                                   const float* __restrict__ V,
                                                   float* __restrict__ O) {
    extern __shared__ float sm[];
    float* qT = sm;                   // [32][132]
    float* kT = qT + 32 * 132;        // [32][132]
    float* vS = kT + 32 * 132;        // [128][34]
    float* S  = vS + 128 * 34;        // [128][132]  (holds P = exp(s - m))

    const int tid = threadIdx.x;
    const int tx = tid & 15, ty = tid >> 4;
    const int b = blockIdx.z, h = blockIdx.y, qt = blockIdx.x;
    const float* qb = Q + ((size_t)(b * NX) + qt * 128) * HD + h * DD;
    const float* kb = K + ((size_t)(b * NY)) * HD + h * DD;
    const float* vb = V + ((size_t)(b * NY)) * HD + h * DD;
    const float scale = 0.17677669529663687f;   // 1/sqrt(32)

    {
        int d4 = (tid & 7) * 4, n0 = tid >> 3;
        #pragma unroll
        for (int rep = 0; rep < 4; rep++) {
            int n = n0 + rep * 32;
            float4 v = *(const float4*)(qb + (size_t)n * HD + d4);
            qT[(d4 + 0) * 132 + n] = v.x * scale;
            qT[(d4 + 1) * 132 + n] = v.y * scale;
            qT[(d4 + 2) * 132 + n] = v.z * scale;
            qT[(d4 + 3) * 132 + n] = v.w * scale;
        }
    }
    float m_i[8], l_i[8];
    float oacc[8][2];
    #pragma unroll
    for (int i = 0; i < 8; i++) {
        m_i[i] = -3.0e38f;
        l_i[i] = 0.0f;
        oacc[i][0] = 0.0f;
        oacc[i][1] = 0.0f;
    }

    for (int t = 0; t < 8; t++) {
        __syncthreads();
        {
            int d4 = (tid & 7) * 4, n0 = tid >> 3;
            #pragma unroll
            for (int rep = 0; rep < 4; rep++) {
                int n = n0 + rep * 32;
                float4 kv = *(const float4*)(kb + (size_t)(t * 128 + n) * HD + d4);
                kT[(d4 + 0) * 132 + n] = kv.x;
                kT[(d4 + 1) * 132 + n] = kv.y;
                kT[(d4 + 2) * 132 + n] = kv.z;
                kT[(d4 + 3) * 132 + n] = kv.w;
                float4 vv = *(const float4*)(vb + (size_t)(t * 128 + n) * HD + d4);
                vS[n * 34 + d4 + 0] = vv.x;
                vS[n * 34 + d4 + 1] = vv.y;
                vS[n * 34 + d4 + 2] = vv.z;
                vS[n * 34 + d4 + 3] = vv.w;
            }
        }
        __syncthreads();
        float s[8][8];
        #pragma unroll
        for (int i = 0; i < 8; i++)
            #pragma unroll
            for (int j = 0; j < 8; j++) s[i][j] = 0.0f;
        #pragma unroll 8
        for (int kk = 0; kk < 32; kk++) {
            float af[8], bf[8];
            ((float4*)af)[0] = *(const float4*)&qT[kk * 132 + ty * 8];
            ((float4*)af)[1] = *(const float4*)&qT[kk * 132 + ty * 8 + 4];
            ((float4*)bf)[0] = *(const float4*)&kT[kk * 132 + tx * 8];
            ((float4*)bf)[1] = *(const float4*)&kT[kk * 132 + tx * 8 + 4];
            #pragma unroll
            for (int i = 0; i < 8; i++)
                #pragma unroll
                for (int j = 0; j < 8; j++)
                    s[i][j] = fmaf(af[i], bf[j], s[i][j]);
        }
        #pragma unroll
        for (int i = 0; i < 8; i++) {
            float mx = s[i][0];
            #pragma unroll
            for (int j = 1; j < 8; j++) mx = fmaxf(mx, s[i][j]);
            #pragma unroll
            for (int o = 1; o < 16; o <<= 1)
                mx = fmaxf(mx, __shfl_xor_sync(0xffffffffu, mx, o));
            float newm = fmaxf(m_i[i], mx);
            float alpha = __expf(m_i[i] - newm);
            float l = 0.0f;
            #pragma unroll
            for (int j = 0; j < 8; j++) {
                float p = __expf(s[i][j] - newm);
                s[i][j] = p;
                l += p;
            }
            #pragma unroll
            for (int o = 1; o < 16; o <<= 1)
                l += __shfl_xor_sync(0xffffffffu, l, o);
            l_i[i] = l_i[i] * alpha + l;
            m_i[i] = newm;
            oacc[i][0] *= alpha;
            oacc[i][1] *= alpha;
        }
        #pragma unroll
        for (int i = 0; i < 8; i++) {
            *(float4*)&S[(ty * 8 + i) * 132 + tx * 8]     = make_float4(s[i][0], s[i][1], s[i][2], s[i][3]);
            *(float4*)&S[(ty * 8 + i) * 132 + tx * 8 + 4] = make_float4(s[i][4], s[i][5], s[i][6], s[i][7]);
        }
        __syncthreads();
        #pragma unroll 4
        for (int j4 = 0; j4 < 32; j4++) {
            float2 vv[4];
            #pragma unroll
            for (int jj = 0; jj < 4; jj++)
                vv[jj] = *(const float2*)&vS[(j4 * 4 + jj) * 34 + tx * 2];
            #pragma unroll
            for (int i = 0; i < 8; i++) {
                float4 p4 = *(const float4*)&S[(ty * 8 + i) * 132 + j4 * 4];
                oacc[i][0] = fmaf(p4.x, vv[0].x, oacc[i][0]);
                oacc[i][1] = fmaf(p4.x, vv[0].y, oacc[i][1]);
                oacc[i][0] = fmaf(p4.y, vv[1].x, oacc[i][0]);
                oacc[i][1] = fmaf(p4.y, vv[1].y, oacc[i][1]);
                oacc[i][0] = fmaf(p4.z, vv[2].x, oacc[i][0]);
                oacc[i][1] = fmaf(p4.z, vv[2].y, oacc[i][1]);
                oacc[i][0] = fmaf(p4.w, vv[3].x, oacc[i][0]);
                oacc[i][1] = fmaf(p4.w, vv[3].y, oacc[i][1]);
            }
        }
    }
    float* ob = O + ((size_t)(b * NX) + qt * 128) * HD + h * DD;
    #pragma unroll
    for (int i = 0; i < 8; i++) {
        int r = ty * 8 + i;
        float inv = 1.0f / l_i[i];
        ob[(size_t)r * HD + tx * 2]     = oacc[i][0] * inv;
        ob[(size_t)r * HD + tx * 2 + 1] = oacc[i][1] * inv;
    }
}

// ---------------- launch ----------------------------------------------------
extern "C" void kernel_launch(void* const* d_in, const int* in_sizes, int n_in,
                              void* d_out, int out_size) {
    const float* x   = (const float*)d_in[0];
    const float* y   = (const float*)d_in[1];
    const float* Wq  = (const float*)d_in[2];
    const float* Wk  = (const float*)d_in[3];
    const float* Wv  = (const float*)d_in[4];
    const float* W1  = (const float*)d_in[5];
    const float* b1  = (const float*)d_in[6];
    const float* g1  = (const float*)d_in[7];
    const float* be1 = (const float*)d_in[8];
    const float* g2  = (const float*)d_in[9];
    const float* be2 = (const float*)d_in[10];
    const float* g3  = (const float*)d_in[11];
    const float* be3 = (const float*)d_in[12];
    const float* W2  = (const float*)d_in[13];
    const float* b2  = (const float*)d_in[14];
    const float* W3  = (const float*)d_in[15];
    const float* b3  = (const float*)d_in[16];
    float* out = (float*)d_out;

    float* base = nullptr;
    cudaGetSymbolAddress((void**)&base, g_scratch);
    float* xn = base + OFF_XN;
    float* yn = base + OFF_YN;
    float* q  = base + OFF_Q;
    float* k  = base + OFF_K;
    float* v  = base + OFF_V;
    float* o  = base + OFF_O;
    float* h0 = base + OFF_H0;
    float* h1 = base + OFF_H1;

    cudaFuncSetAttribute(attn_kernel, cudaFuncAttributeMaxDynamicSharedMemorySize, ATTN_SMEM);

    // 1. LayerNorms of both inputs (single launch)
    ln2_kernel<<<2 * MROWS, 256>>>(x, xn, g1, be1, y, yn, g2, be2);

    // 2. QKV projections (single launch, z-dispatch; packed [H,C,32] weights)
    qkv_kernel<<<dim3(HD / 128, MROWS / 128, 3), 256>>>(xn, yn, Wq, Wk, Wv, q, k, v);

    // 3. Attention
    attn_kernel<<<dim3(NX / 128, HH, BB), 256, ATTN_SMEM>>>(q, k, v, o);

    // 4. out0 = xn + o @ W1 + b1   (stored in d_out)
    sgemm_kernel<1, 0, HD><<<dim3(C1 / 128, MROWS / 128), 256>>>(o, W1, out, C1, b1, xn);

    // 5. h0 = LN(out0)
    ln_kernel<<<MROWS, 256>>>(out, h0, g3, be3);

    // 6. h1 = gelu(h0 @ W2 + b2)
    sgemm_kernel<2, 0, C1><<<dim3((WW * C1) / 128, MROWS / 128), 256>>>(h0, W2, h1, WW * C1, b2, nullptr);

    // 7. out = out0 + h1 @ W3 + b3
    sgemm_kernel<1, 0, WW * C1><<<dim3(C1 / 128, MROWS / 128), 256>>>(h1, W3, out, C1, b3, out);
}